// round 1
// baseline (speedup 1.0000x reference)
#include <cuda_runtime.h>
#include <math.h>

#define NEGV -1e30f

// ---- scratch (static device memory; no allocations) ----
__device__ float g_S[4 * 512 * 512];   // score matrices, 4 MB
__device__ float g_n2[2 * 4 * 512];    // row norms: [0,2048)=x rows, [2048,4096)=y rows
__device__ float g_pm[256];            // partial LSE max
__device__ float g_ps[256];            // partial LSE sum

// ================= norms: ||x_i||^2 and ||y_j||^2 =================
__global__ void norm_kernel(const float* __restrict__ x, const float* __restrict__ y) {
    int w = (blockIdx.x * blockDim.x + threadIdx.x) >> 5;  // global warp id, 0..255
    int lane = threadIdx.x & 31;
    #pragma unroll
    for (int s = 0; s < 16; s++) {
        int row = w + s * 256;   // 0..4095
        const float* p = (row < 2048) ? (x + row * 128) : (y + (row - 2048) * 128);
        float v0 = p[lane], v1 = p[lane + 32], v2 = p[lane + 64], v3 = p[lane + 96];
        float sum = v0 * v0 + v1 * v1 + v2 * v2 + v3 * v3;
        #pragma unroll
        for (int o = 16; o > 0; o >>= 1) sum += __shfl_xor_sync(0xffffffffu, sum, o);
        if (lane == 0) g_n2[row] = sum;
    }
}

// ================= S = x2 + y2 - 2 x.y  (64x64 tiles) =================
__global__ void __launch_bounds__(256) dist_kernel(const float* __restrict__ x,
                                                   const float* __restrict__ y) {
    int b = blockIdx.z;
    int i0 = blockIdx.y * 64, j0 = blockIdx.x * 64;
    const float* xb = x + (b * 512 + i0) * 128;
    const float* yb = y + (b * 512 + j0) * 128;
    __shared__ float xs[16][64];
    __shared__ float ys[16][64];
    int tid = threadIdx.x;
    int tx = tid & 15, ty = tid >> 4;
    float acc[4][4];
    #pragma unroll
    for (int r = 0; r < 4; r++)
        #pragma unroll
        for (int c = 0; c < 4; c++) acc[r][c] = 0.f;

    for (int kc = 0; kc < 128; kc += 16) {
        __syncthreads();
        #pragma unroll
        for (int l = 0; l < 4; l++) {
            int e = tid + l * 256;
            int r = e >> 4, kk = e & 15;
            xs[kk][r] = xb[r * 128 + kc + kk];
            ys[kk][r] = yb[r * 128 + kc + kk];
        }
        __syncthreads();
        #pragma unroll
        for (int kk = 0; kk < 16; kk++) {
            float4 a  = *(const float4*)&xs[kk][ty * 4];
            float4 bv = *(const float4*)&ys[kk][tx * 4];
            float ar[4] = {a.x, a.y, a.z, a.w};
            float br[4] = {bv.x, bv.y, bv.z, bv.w};
            #pragma unroll
            for (int r = 0; r < 4; r++)
                #pragma unroll
                for (int c = 0; c < 4; c++)
                    acc[r][c] = fmaf(ar[r], br[c], acc[r][c]);
        }
    }
    float x2[4], y2[4];
    #pragma unroll
    for (int r = 0; r < 4; r++) x2[r] = g_n2[b * 512 + i0 + ty * 4 + r];
    #pragma unroll
    for (int c = 0; c < 4; c++) y2[c] = g_n2[2048 + b * 512 + j0 + tx * 4 + c];
    float* Sb = g_S + b * 262144;
    #pragma unroll
    for (int r = 0; r < 4; r++) {
        float4 o;
        o.x = x2[r] + y2[0] - 2.f * acc[r][0];
        o.y = x2[r] + y2[1] - 2.f * acc[r][1];
        o.z = x2[r] + y2[2] - 2.f * acc[r][2];
        o.w = x2[r] + y2[3] - 2.f * acc[r][3];
        *(float4*)&Sb[(i0 + ty * 4 + r) * 512 + j0 + tx * 4] = o;
    }
}

// ================= wavefront soft-SW; 1 CTA per batch, 2 columns/thread =================
// Thread t owns columns (1-based) jA=2t+1, jB=2t+2. Superstep u computes row i=u-t+1.
// Neighbor (thread t-1) B-column values are passed via shfl_up (+ shared at warp edges):
//  - fresh (superstep u-1)  -> left deps of cell A
//  - stale (superstep u-2)  -> diagonal deps of cell A
__global__ void __launch_bounds__(256) sw_kernel(const float* __restrict__ go,
                                                 const float* __restrict__ ge,
                                                 float* __restrict__ out) {
    const int b = blockIdx.x;
    const int t = threadIdx.x;
    const int warp = t >> 5, lane = t & 31;
    const float2* S2  = (const float2*)(g_S + b * 262144);
    const float2* go2 = (const float2*)go;
    const float2* ge2 = (const float2*)ge;
    float* Pb = out + 1 + b * 262144;

    __shared__ float sh[2][8][4];   // [parity][warp][d,ix,iy,pad]
    if (t < 64) ((float*)sh)[t] = NEGV;

    float Ad = NEGV, Aix = NEGV, Aiy = NEGV;   // own col A, previous row
    float Bd = NEGV, Bix = NEGV, Biy = NEGV;   // own col B, previous row
    float o2d = NEGV, o2ix = NEGV, o2iy = NEGV; // neighbor B, two supersteps ago

    float2 sP, goP, geP;
    {   // prefetch for u = 0 (row i = 1 - t; only t==0 valid)
        int i = 1 - t;
        bool v = (i >= 1);
        int idx = (i - 1) * 256 + t;
        sP  = v ? S2[idx]  : make_float2(0.f, 0.f);
        goP = v ? go2[idx] : make_float2(0.f, 0.f);
        geP = v ? ge2[idx] : make_float2(0.f, 0.f);
    }
    __syncthreads();

    for (int u = 0; u < 767; u++) {
        float2 sC = sP, goC = goP, geC = geP;
        // neighbor fresh values (its superstep u-1 results)
        float nd  = __shfl_up_sync(0xffffffffu, Bd, 1);
        float nix = __shfl_up_sync(0xffffffffu, Bix, 1);
        float niy = __shfl_up_sync(0xffffffffu, Biy, 1);
        if (lane == 0) {
            if (warp == 0) { nd = NEGV; nix = NEGV; niy = NEGV; }
            else {
                int p = (u + 1) & 1;   // buffer written at superstep u-1
                nd  = sh[p][warp - 1][0];
                nix = sh[p][warp - 1][1];
                niy = sh[p][warp - 1][2];
            }
        }
        // prefetch for u+1 (row i = u+2-t)
        {
            int i = u + 2 - t;
            bool v = (i >= 1) && (i <= 512);
            int idx = (i - 1) * 256 + t;
            if (v) { sP = S2[idx]; goP = go2[idx]; geP = ge2[idx]; }
        }

        bool active = (u >= t) && (u <= t + 511);
        if (active) {
            // ---- cell A (col 2t+1) ----
            float a1 = nd - goC.x, c1 = nix - geC.x;           // left = neighbor fresh
            float mx1 = fmaxf(a1, c1);
            float ixA = mx1 + __logf(1.0f + __expf(fminf(a1, c1) - mx1));

            float m3 = fmaxf(fmaxf(o2d, o2ix), o2iy);          // diag = neighbor stale
            float m  = fmaxf(m3, 0.0f);
            float dA = sC.x + m + __logf(__expf(o2d - m) + __expf(o2ix - m) +
                                         __expf(o2iy - m) + __expf(-m));

            float p1 = Ad - goC.x, q1 = Aix - goC.x, r1 = Aiy - geC.x;  // up = own A prev
            float m4 = fmaxf(fmaxf(p1, q1), r1);
            float iyA = m4 + __logf(__expf(p1 - m4) + __expf(q1 - m4) + __expf(r1 - m4));

            // ---- cell B (col 2t+2) ----
            float a2 = dA - goC.y, c2 = ixA - geC.y;           // left = A current
            float mx2 = fmaxf(a2, c2);
            float ixB = mx2 + __logf(1.0f + __expf(fminf(a2, c2) - mx2));

            float m5 = fmaxf(fmaxf(Ad, Aix), Aiy);             // diag = own A prev
            float m6 = fmaxf(m5, 0.0f);
            float dB = sC.y + m6 + __logf(__expf(Ad - m6) + __expf(Aix - m6) +
                                          __expf(Aiy - m6) + __expf(-m6));

            float p2 = Bd - goC.y, q2 = Bix - goC.y, r2 = Biy - geC.y;  // up = own B prev
            float m7 = fmaxf(fmaxf(p2, q2), r2);
            float iyB = m7 + __logf(__expf(p2 - m7) + __expf(q2 - m7) + __expf(r2 - m7));

            int row = u - t;                  // 0-based output row
            Pb[row * 512 + 2 * t]     = dA;
            Pb[row * 512 + 2 * t + 1] = dB;

            Ad = dA; Aix = ixA; Aiy = iyA;
            Bd = dB; Bix = ixB; Biy = iyB;
        }
        o2d = nd; o2ix = nix; o2iy = niy;     // fresh -> stale for next superstep

        if (lane == 31) {                      // publish warp-boundary B values (step u)
            sh[u & 1][warp][0] = Bd;
            sh[u & 1][warp][1] = Bix;
            sh[u & 1][warp][2] = Biy;
        }
        __syncthreads();
    }
}

// ================= value = LSE over all D, loss = mean over batches =================
__global__ void lse_part(const float* __restrict__ out) {
    int b = blockIdx.y, chunk = blockIdx.x, t = threadIdx.x;
    const float* P = out + 1 + b * 262144 + chunk * 4096;
    float m = NEGV, s = 0.f;
    #pragma unroll
    for (int i = 0; i < 16; i++) {
        float d = P[t + i * 256];
        float nm = fmaxf(m, d);
        s = s * __expf(m - nm) + __expf(d - nm);
        m = nm;
    }
    __shared__ float sm[256], ss[256];
    sm[t] = m; ss[t] = s;
    __syncthreads();
    for (int o = 128; o > 0; o >>= 1) {
        if (t < o) {
            float m2 = sm[t + o], s2 = ss[t + o];
            float nm = fmaxf(sm[t], m2);
            ss[t] = ss[t] * __expf(sm[t] - nm) + s2 * __expf(m2 - nm);
            sm[t] = nm;
        }
        __syncthreads();
    }
    if (t == 0) { g_pm[b * 64 + chunk] = sm[0]; g_ps[b * 64 + chunk] = ss[0]; }
}

__global__ void lse_final(float* __restrict__ out) {
    int t = threadIdx.x;
    __shared__ float sm[256], ss[256], vv[4];
    sm[t] = g_pm[t]; ss[t] = g_ps[t];
    __syncthreads();
    for (int o = 32; o > 0; o >>= 1) {
        if ((t & 63) < o) {
            float m2 = sm[t + o], s2 = ss[t + o];
            float nm = fmaxf(sm[t], m2);
            ss[t] = ss[t] * __expf(sm[t] - nm) + s2 * __expf(m2 - nm);
            sm[t] = nm;
        }
        __syncthreads();
    }
    if ((t & 63) == 0) vv[t >> 6] = sm[t] + logf(ss[t]);
    __syncthreads();
    if (t == 0) out[0] = 0.25f * (vv[0] + vv[1] + vv[2] + vv[3]);
}

// ================= launcher =================
extern "C" void kernel_launch(void* const* d_in, const int* in_sizes, int n_in,
                              void* d_out, int out_size) {
    const float* x  = (const float*)d_in[0];
    const float* y  = (const float*)d_in[1];
    const float* go = (const float*)d_in[2];
    const float* ge = (const float*)d_in[3];
    float* out = (float*)d_out;

    norm_kernel<<<32, 256>>>(x, y);
    dist_kernel<<<dim3(8, 8, 4), 256>>>(x, y);
    sw_kernel<<<4, 256>>>(go, ge, out);
    lse_part<<<dim3(64, 4), 256>>>(out);
    lse_final<<<1, 256>>>(out);
}